// round 11
// baseline (speedup 1.0000x reference)
#include <cuda_runtime.h>
#include <cuda_bf16.h>
#include <mma.h>
#include <math.h>
#include <stdint.h>

using namespace nvcuda;

static const int MAXN = 50000;
static const int MAXE = 800000 + MAXN;

// ---------------- scratch ----------------
__device__ float g_h1[(MAXN + 128) * 256];   // +128 rows pad for full-tile stores
__device__ float g_o1[MAXN * 256];
__device__ float g_as1[MAXN * 8];
__device__ float g_ad1[MAXN * 8];
__device__ float g_h2[MAXN * 32];
__device__ float g_z[MAXN * 32];
__device__ float g_as2[MAXN];
__device__ float g_ad2[MAXN];
__device__ int   g_cnt[MAXN];
__device__ int   g_row[MAXN + 1];
__device__ int   g_cur[MAXN];
__device__ int   g_bsum[256];
__device__ int   g_boff[256];
__device__ int   g_esrc[MAXE];
__device__ __nv_bfloat16 g_xhi[MAXN * 128];
__device__ __nv_bfloat16 g_xlo[MAXN * 128];
__device__ __nv_bfloat16 g_wthi[256 * 128];
__device__ __nv_bfloat16 g_wtlo[256 * 128];

__device__ __forceinline__ float lrelu(float v) { return v > 0.f ? v : 0.2f * v; }

// ================= GEMM1 wmma bf16 split + fused alpha8 =================
// h1[M,256] = x[M,128] @ W1[128,256]; acc = xhi*whi + xhi*wlo + xlo*whi.
// CTA: 128x128 tile (4 heads), 16 warps 32x32. Epilogue: acc -> smem ->
// per-row/per-head alpha dots + coalesced h1 store.
static const int LDM = 136;                       // bf16 smem leading dim
static const int CLD = 132;                       // fp32 epilogue leading dim
static const int WSM_TOTAL = 4 * 128 * LDM * 2;   // 139264 (>= 128*132*4)

__global__ __launch_bounds__(512, 1)
void gemm1_wmma_k(const __nv_bfloat16* __restrict__ xhi, const __nv_bfloat16* __restrict__ xlo,
                  const __nv_bfloat16* __restrict__ wthi, const __nv_bfloat16* __restrict__ wtlo,
                  const float* __restrict__ aS1, const float* __restrict__ aD1,
                  float* __restrict__ out, float* __restrict__ as, float* __restrict__ ad,
                  int M) {
    extern __shared__ char smraw[];
    __nv_bfloat16* Ah = (__nv_bfloat16*)smraw;
    __nv_bfloat16* Al = Ah + 128 * LDM;
    __nv_bfloat16* Bh = Al + 128 * LDM;
    __nv_bfloat16* Bl = Bh + 128 * LDM;
    float* Csf = (float*)smraw;                   // epilogue reuse
    int tid = threadIdx.x, wid = tid >> 5, lane = tid & 31;
    int m0 = blockIdx.y * 128, n0 = blockIdx.x * 128;

    for (int idx = tid; idx < 128 * 16; idx += 512) {
        int r = idx >> 4, c = idx & 15;
        uint4 vh = make_uint4(0u, 0u, 0u, 0u), vl = make_uint4(0u, 0u, 0u, 0u);
        if (m0 + r < M) {
            vh = ((const uint4*)xhi)[(size_t)(m0 + r) * 16 + c];
            vl = ((const uint4*)xlo)[(size_t)(m0 + r) * 16 + c];
        }
        ((uint4*)(Ah + r * LDM))[c] = vh;
        ((uint4*)(Al + r * LDM))[c] = vl;
    }
    for (int idx = tid; idx < 128 * 16; idx += 512) {
        int r = idx >> 4, c = idx & 15;
        ((uint4*)(Bh + r * LDM))[c] = ((const uint4*)wthi)[(size_t)(n0 + r) * 16 + c];
        ((uint4*)(Bl + r * LDM))[c] = ((const uint4*)wtlo)[(size_t)(n0 + r) * 16 + c];
    }
    __syncthreads();

    int wr = wid & 3, wc = wid >> 2;   // warp tile: rows wr*32..+31, cols wc*32..+31
    wmma::fragment<wmma::accumulator, 16, 16, 16, float> acc[2][2];
    #pragma unroll
    for (int i = 0; i < 2; i++)
        #pragma unroll
        for (int j = 0; j < 2; j++) wmma::fill_fragment(acc[i][j], 0.f);

    #pragma unroll
    for (int p = 0; p < 3; p++) {
        const __nv_bfloat16* Ab = (p == 2) ? Al : Ah;
        const __nv_bfloat16* Bb = (p == 1) ? Bl : Bh;
        #pragma unroll
        for (int k = 0; k < 128; k += 16) {
            wmma::fragment<wmma::matrix_a, 16, 16, 16, __nv_bfloat16, wmma::row_major> af[2];
            wmma::fragment<wmma::matrix_b, 16, 16, 16, __nv_bfloat16, wmma::col_major> bf[2];
            #pragma unroll
            for (int i = 0; i < 2; i++)
                wmma::load_matrix_sync(af[i], Ab + (wr * 32 + i * 16) * LDM + k, LDM);
            #pragma unroll
            for (int j = 0; j < 2; j++)
                wmma::load_matrix_sync(bf[j], Bb + (wc * 32 + j * 16) * LDM + k, LDM);
            #pragma unroll
            for (int i = 0; i < 2; i++)
                #pragma unroll
                for (int j = 0; j < 2; j++)
                    wmma::mma_sync(acc[i][j], af[i], bf[j], acc[i][j]);
        }
    }
    __syncthreads();   // done reading tiles; safe to overwrite smem

    // acc -> smem (fp32, CLD-padded)
    #pragma unroll
    for (int i = 0; i < 2; i++)
        #pragma unroll
        for (int j = 0; j < 2; j++)
            wmma::store_matrix_sync(Csf + (wr * 32 + i * 16) * CLD + wc * 32 + j * 16,
                                    acc[i][j], CLD, wmma::mem_row_major);
    __syncthreads();

    // fused alpha: CTA heads hb..hb+3; warp w -> rows w*8..+7
    {
        int hb = n0 >> 5;
        int hl = lane >> 3, k4 = lane & 7;
        float4 cs = ((const float4*)aS1)[(hb + hl) * 8 + k4];
        float4 cd = ((const float4*)aD1)[(hb + hl) * 8 + k4];
        #pragma unroll
        for (int rr = 0; rr < 8; rr++) {
            int r = wid * 8 + rr;
            float4 v = *(float4*)&Csf[r * CLD + hl * 32 + k4 * 4];
            float ps = v.x * cs.x + v.y * cs.y + v.z * cs.z + v.w * cs.w;
            float pd = v.x * cd.x + v.y * cd.y + v.z * cd.z + v.w * cd.w;
            #pragma unroll
            for (int off = 4; off; off >>= 1) {
                ps += __shfl_xor_sync(0xffffffffu, ps, off);
                pd += __shfl_xor_sync(0xffffffffu, pd, off);
            }
            int gr = m0 + r;
            if (k4 == 0 && gr < M) {
                as[gr * 8 + hb + hl] = ps;
                ad[gr * 8 + hb + hl] = pd;
            }
        }
    }
    // coalesced h1 store (pad rows beyond M exist)
    for (int idx = tid; idx < 128 * 32; idx += 512) {
        int r = idx >> 5, c4 = idx & 31;
        *(float4*)(out + (size_t)(m0 + r) * 256 + n0 + c4 * 4) =
            *(float4*)&Csf[r * CLD + c4 * 4];
    }
}

// ---------------- merged conversions (x split + W1t split) ----------------
__global__ void conv_k(const float4* __restrict__ x4, uint2* __restrict__ xhi,
                       uint2* __restrict__ xlo, int n4,
                       const float* __restrict__ W1,
                       __nv_bfloat16* __restrict__ whi, __nv_bfloat16* __restrict__ wlo) {
    int nxb = (n4 + 255) >> 8;
    if ((int)blockIdx.x < nxb) {
        int i = blockIdx.x * 256 + threadIdx.x;
        if (i >= n4) return;
        float4 v = x4[i];
        __nv_bfloat162 h01 = __floats2bfloat162_rn(v.x, v.y);
        __nv_bfloat162 h23 = __floats2bfloat162_rn(v.z, v.w);
        __nv_bfloat162 l01 = __floats2bfloat162_rn(v.x - __bfloat162float(h01.x),
                                                   v.y - __bfloat162float(h01.y));
        __nv_bfloat162 l23 = __floats2bfloat162_rn(v.z - __bfloat162float(h23.x),
                                                   v.w - __bfloat162float(h23.y));
        uint2 hp, lp;
        hp.x = *(uint32_t*)&h01; hp.y = *(uint32_t*)&h23;
        lp.x = *(uint32_t*)&l01; lp.y = *(uint32_t*)&l23;
        xhi[i] = hp;
        xlo[i] = lp;
    } else {
        int i = (blockIdx.x - nxb) * 256 + threadIdx.x;   // Wt[n,k] <- W[k,n]
        if (i >= 256 * 128) return;
        int n = i >> 7, k = i & 127;
        float v = W1[k * 256 + n];
        __nv_bfloat16 h = __float2bfloat16(v);
        whi[i] = h;
        wlo[i] = __float2bfloat16(v - __bfloat162float(h));
    }
}

// ---------------- GEMM 128x64 SIMT (+optional fused alpha1 when N==32) ----
__global__ void gemm_k(const float* __restrict__ A, const float* __restrict__ B,
                       const float* __restrict__ bias, float* __restrict__ C,
                       int M, int N, int K, int reluA,
                       const float* __restrict__ aS, const float* __restrict__ aD,
                       float* __restrict__ als, float* __restrict__ ald) {
    __shared__ float As[16][132];
    __shared__ float Bs[16][64];
    int tid = threadIdx.x;
    int ty = tid >> 4;
    int tx = tid & 15;
    int m0 = blockIdx.y * 128;
    int n0 = blockIdx.x * 64;
    float acc[8][4] = {};

    for (int k0 = 0; k0 < K; k0 += 16) {
        #pragma unroll
        for (int i = 0; i < 2; i++) {
            int L = tid + 256 * i;
            int row = L >> 2, q = (L & 3) << 2;
            float4 v = make_float4(0.f, 0.f, 0.f, 0.f);
            if (m0 + row < M) {
                v = *(const float4*)(A + (size_t)(m0 + row) * K + k0 + q);
                if (reluA) {
                    v.x = fmaxf(v.x, 0.f); v.y = fmaxf(v.y, 0.f);
                    v.z = fmaxf(v.z, 0.f); v.w = fmaxf(v.w, 0.f);
                }
            }
            As[q + 0][row] = v.x; As[q + 1][row] = v.y;
            As[q + 2][row] = v.z; As[q + 3][row] = v.w;
        }
        {
            int kl = tid >> 4, g = (tid & 15) << 2;
            float4 v = make_float4(0.f, 0.f, 0.f, 0.f);
            if (n0 + g < N)
                v = *(const float4*)(B + (size_t)(k0 + kl) * N + n0 + g);
            *(float4*)&Bs[kl][g] = v;
        }
        __syncthreads();
        #pragma unroll
        for (int kk = 0; kk < 16; kk++) {
            float a[8], b[4];
            *(float4*)&a[0] = *(const float4*)&As[kk][ty * 8];
            *(float4*)&a[4] = *(const float4*)&As[kk][ty * 8 + 4];
            *(float4*)&b[0] = *(const float4*)&Bs[kk][tx * 4];
            #pragma unroll
            for (int i = 0; i < 8; i++)
                #pragma unroll
                for (int j = 0; j < 4; j++)
                    acc[i][j] += a[i] * b[j];
        }
        __syncthreads();
    }
    int colb = n0 + tx * 4;
    if (colb < N) {
        float4 bv = make_float4(0.f, 0.f, 0.f, 0.f);
        if (bias) bv = *(const float4*)(bias + colb);
        #pragma unroll
        for (int i = 0; i < 8; i++) {
            int row = m0 + ty * 8 + i;
            if (row >= M) break;
            float4 v = make_float4(acc[i][0] + bv.x, acc[i][1] + bv.y,
                                   acc[i][2] + bv.z, acc[i][3] + bv.w);
            *(float4*)(C + (size_t)row * N + colb) = v;
        }
    }
    // fused alpha1 (only used for GEMM2: N==32, cols live in tx<8)
    if (als) {
        float4 cs = make_float4(0.f, 0.f, 0.f, 0.f), cd = cs;
        if (tx < 8) {
            cs = ((const float4*)aS)[tx];
            cd = ((const float4*)aD)[tx];
        }
        #pragma unroll
        for (int i = 0; i < 8; i++) {
            float ps = acc[i][0] * cs.x + acc[i][1] * cs.y + acc[i][2] * cs.z + acc[i][3] * cs.w;
            float pd = acc[i][0] * cd.x + acc[i][1] * cd.y + acc[i][2] * cd.z + acc[i][3] * cd.w;
            #pragma unroll
            for (int off = 8; off; off >>= 1) {
                ps += __shfl_xor_sync(0xffffffffu, ps, off);
                pd += __shfl_xor_sync(0xffffffffu, pd, off);
            }
            int row = m0 + ty * 8 + i;
            if (tx == 0 && row < M) { als[row] = ps; ald[row] = pd; }
        }
    }
}

// ---------------- CSR build ----------------
__global__ void init_cnt_k(int* cnt, int N) {
    int i = blockIdx.x * blockDim.x + threadIdx.x;
    if (i < N) cnt[i] = 1;
}
__global__ void hist_k(int* cnt, const int* __restrict__ dst, int E) {
    int e = blockIdx.x * blockDim.x + threadIdx.x;
    if (e < E) atomicAdd(&cnt[dst[e]], 1);
}
__global__ void scanA_k(const int* __restrict__ cnt, int* bsum, int N) {
    __shared__ int sm[256];
    int gi = blockIdx.x * 256 + threadIdx.x;
    int v = (gi < N) ? cnt[gi] : 0;
    sm[threadIdx.x] = v; __syncthreads();
    for (int off = 128; off; off >>= 1) {
        if (threadIdx.x < off) sm[threadIdx.x] += sm[threadIdx.x + off];
        __syncthreads();
    }
    if (threadIdx.x == 0) bsum[blockIdx.x] = sm[0];
}
__global__ void scanB_k(const int* __restrict__ bsum, int* boff, int nb) {
    __shared__ int sm[256];
    int t = threadIdx.x;
    int v = (t < nb) ? bsum[t] : 0;
    sm[t] = v; __syncthreads();
    #pragma unroll
    for (int off = 1; off < 256; off <<= 1) {
        int x = (t >= off) ? sm[t - off] : 0;
        __syncthreads();
        sm[t] += x;
        __syncthreads();
    }
    if (t < nb) boff[t] = sm[t] - v;
}
__global__ void scanC_k(const int* __restrict__ cnt, const int* __restrict__ boff,
                        int* row, int* cur, int N) {
    __shared__ int sm[256];
    int t = threadIdx.x;
    int gi = blockIdx.x * 256 + t;
    int v = (gi < N) ? cnt[gi] : 0;
    sm[t] = v; __syncthreads();
    #pragma unroll
    for (int off = 1; off < 256; off <<= 1) {
        int x = (t >= off) ? sm[t - off] : 0;
        __syncthreads();
        sm[t] += x;
        __syncthreads();
    }
    int excl = boff[blockIdx.x] + sm[t] - v;
    if (gi < N) { row[gi] = excl; cur[gi] = excl; }
    if (gi == N - 1) row[N] = excl + v;
}
__global__ void scatter_k(const int* __restrict__ src, const int* __restrict__ dst,
                          int* cur, int* esrc, int E, int ET) {
    int e = blockIdx.x * blockDim.x + threadIdx.x;
    if (e >= ET) return;
    int s_, d_;
    if (e < E) { s_ = src[e]; d_ = dst[e]; } else { s_ = d_ = e - E; }
    int pos = atomicAdd(&cur[d_], 1);
    esrc[pos] = s_;
}

// ---------------- fused GAT aggregate, layer 1 (H=8, C=32): warp per dst ----
__global__ void gat8_k(const float* __restrict__ h1,
                       const float* __restrict__ as, const float* __restrict__ ad,
                       const int* __restrict__ row, const int* __restrict__ esrc,
                       const float* __restrict__ bias, float* __restrict__ out, int N) {
    int w = (blockIdx.x * blockDim.x + threadIdx.x) >> 5;
    int l = threadIdx.x & 31;
    if (w >= N) return;
    int hgrp = l >> 2;
    int rs = row[w], re = row[w + 1];
    float adh = ad[w * 8 + hgrp];

    float mx = -3.0e38f;
    int s = esrc[rs];
    for (int i = rs; i < re; i++) {
        int sn = (i + 1 < re) ? esrc[i + 1] : 0;
        float v = lrelu(__ldg(as + s * 8 + hgrp) + adh);
        mx = fmaxf(mx, v);
        s = sn;
    }
    float sum = 0.f;
    float4 acc0 = make_float4(0.f, 0.f, 0.f, 0.f);
    float4 acc1 = make_float4(0.f, 0.f, 0.f, 0.f);
    s = esrc[rs];
    for (int i = rs; i < re; i++) {
        int sn = (i + 1 < re) ? esrc[i + 1] : 0;
        float v = lrelu(__ldg(as + s * 8 + hgrp) + adh);
        float ex = expf(v - mx);
        sum += ex;
        const float4* hp = (const float4*)(h1 + (size_t)s * 256);
        float4 a = hp[2 * l], b = hp[2 * l + 1];
        acc0.x += ex * a.x; acc0.y += ex * a.y; acc0.z += ex * a.z; acc0.w += ex * a.w;
        acc1.x += ex * b.x; acc1.y += ex * b.y; acc1.z += ex * b.z; acc1.w += ex * b.w;
        s = sn;
    }
    float inv = 1.f / (sum + 1e-16f);
    float4 b0 = ((const float4*)bias)[2 * l];
    float4 b1 = ((const float4*)bias)[2 * l + 1];
    float4 o0 = make_float4(acc0.x * inv + b0.x, acc0.y * inv + b0.y,
                            acc0.z * inv + b0.z, acc0.w * inv + b0.w);
    float4 o1 = make_float4(acc1.x * inv + b1.x, acc1.y * inv + b1.y,
                            acc1.z * inv + b1.z, acc1.w * inv + b1.w);
    float4* op = (float4*)(out + (size_t)w * 256);
    op[2 * l] = o0; op[2 * l + 1] = o1;
}

// ---------------- fused GAT aggregate, layer 2 (H=1, C=32): warp per dst ----
__global__ void gat1_k(const float* __restrict__ h2,
                       const float* __restrict__ as, const float* __restrict__ ad,
                       const int* __restrict__ row, const int* __restrict__ esrc,
                       const float* __restrict__ bias, float* __restrict__ out, int N) {
    int w = (blockIdx.x * blockDim.x + threadIdx.x) >> 5;
    int l = threadIdx.x & 31;
    if (w >= N) return;
    int rs = row[w], re = row[w + 1];
    float adh = ad[w];

    float mx = -3.0e38f;
    int s = esrc[rs];
    for (int i = rs; i < re; i++) {
        int sn = (i + 1 < re) ? esrc[i + 1] : 0;
        float v = lrelu(__ldg(as + s) + adh);
        mx = fmaxf(mx, v);
        s = sn;
    }
    float sum = 0.f, acc = 0.f;
    s = esrc[rs];
    for (int i = rs; i < re; i++) {
        int sn = (i + 1 < re) ? esrc[i + 1] : 0;
        float v = lrelu(__ldg(as + s) + adh);
        float ex = expf(v - mx);
        sum += ex;
        acc += ex * __ldg(h2 + (size_t)s * 32 + l);
        s = sn;
    }
    out[(size_t)w * 32 + l] = acc / (sum + 1e-16f) + bias[l];
}

// ---------------- launch ----------------
extern "C" void kernel_launch(void* const* d_in, const int* in_sizes, int n_in,
                              void* d_out, int out_size) {
    const float* x   = (const float*)d_in[0];
    const int*   ei  = (const int*)d_in[1];
    const float* W1  = (const float*)d_in[2];
    const float* aS1 = (const float*)d_in[3];
    const float* aD1 = (const float*)d_in[4];
    const float* b1  = (const float*)d_in[5];
    const float* W2  = (const float*)d_in[6];
    const float* aS2 = (const float*)d_in[7];
    const float* aD2 = (const float*)d_in[8];
    const float* b2  = (const float*)d_in[9];
    const float* Wd  = (const float*)d_in[10];
    const float* bd  = (const float*)d_in[11];
    float* out = (float*)d_out;

    int N  = in_sizes[0] / 128;
    int E  = in_sizes[1] / 2;
    int ET = E + N;
    const int* src = ei;
    const int* dst = ei + E;

    float *h1, *o1, *as1, *ad1, *h2, *z, *as2, *ad2;
    int *cnt, *row, *cur, *bsum, *boff, *esrc;
    __nv_bfloat16 *xhi, *xlo, *wthi, *wtlo;
    cudaGetSymbolAddress((void**)&h1,   g_h1);
    cudaGetSymbolAddress((void**)&o1,   g_o1);
    cudaGetSymbolAddress((void**)&as1,  g_as1);
    cudaGetSymbolAddress((void**)&ad1,  g_ad1);
    cudaGetSymbolAddress((void**)&h2,   g_h2);
    cudaGetSymbolAddress((void**)&z,    g_z);
    cudaGetSymbolAddress((void**)&as2,  g_as2);
    cudaGetSymbolAddress((void**)&ad2,  g_ad2);
    cudaGetSymbolAddress((void**)&cnt,  g_cnt);
    cudaGetSymbolAddress((void**)&row,  g_row);
    cudaGetSymbolAddress((void**)&cur,  g_cur);
    cudaGetSymbolAddress((void**)&bsum, g_bsum);
    cudaGetSymbolAddress((void**)&boff, g_boff);
    cudaGetSymbolAddress((void**)&esrc, g_esrc);
    cudaGetSymbolAddress((void**)&xhi,  g_xhi);
    cudaGetSymbolAddress((void**)&xlo,  g_xlo);
    cudaGetSymbolAddress((void**)&wthi, g_wthi);
    cudaGetSymbolAddress((void**)&wtlo, g_wtlo);

    cudaFuncSetAttribute(gemm1_wmma_k, cudaFuncAttributeMaxDynamicSharedMemorySize, WSM_TOTAL);

    const int TB = 256;
    int mb = (N + 127) / 128;
    int nb = (N + 255) / 256;
    int n4 = N * 32;                    // float4 count of x
    int nxb = (n4 + 255) / 256;

    init_cnt_k<<<nb, TB>>>(cnt, N);                                    // 1
    hist_k<<<(E + TB - 1) / TB, TB>>>(cnt, dst, E);                    // 2
    conv_k<<<nxb + 128, TB>>>((const float4*)x, (uint2*)xhi, (uint2*)xlo, n4,
                              W1, wthi, wtlo);                         // 3
    gemm1_wmma_k<<<dim3(2, mb), 512, WSM_TOTAL>>>(xhi, xlo, wthi, wtlo,
                                                  aS1, aD1, h1, as1, ad1, N); // 4 (profiled)
    scanA_k<<<nb, TB>>>(cnt, bsum, N);                                 // 5
    scanB_k<<<1, TB>>>(bsum, boff, nb);                                // 6
    scanC_k<<<nb, TB>>>(cnt, boff, row, cur, N);                       // 7
    scatter_k<<<(ET + TB - 1) / TB, TB>>>(src, dst, cur, esrc, E, ET); // 8

    // ===== Layer 1 aggregate =====
    gat8_k<<<(N * 32 + TB - 1) / TB, TB>>>(h1, as1, ad1, row, esrc, b1, o1, N); // 9

    // ===== Layer 2: GEMM2 (relu fused, alpha1 fused) =====
    gemm_k<<<dim3(1, mb), TB>>>(o1, W2, nullptr, h2, N, 32, 256, 1,
                                aS2, aD2, as2, ad2);                   // 10
    gat1_k<<<(N * 32 + TB - 1) / TB, TB>>>(h2, as2, ad2, row, esrc, b2, z, N);  // 11

    // ===== Decoder =====
    gemm_k<<<dim3(2, mb), TB>>>(z, Wd, bd, out, N, 128, 32, 0,
                                nullptr, nullptr, nullptr, nullptr);   // 12
}